// round 4
// baseline (speedup 1.0000x reference)
#include <cuda_runtime.h>
#include <cstdint>

// LoRA linear via rank-16 factor:
//   t   = x @ A^T   : [16384,4096] @ [4096,16] -> [16384,16]   (stage 1)
//   out = t @ B^T   : [16384,16]   @ [16,4096] -> [16384,4096] (stage 2)

#define D 4096
#define R 16
#define ROWS_TOTAL 16384
#define KC 128            // k per chunk
#define NCHUNK (D / KC)   // 32

typedef unsigned long long u64;

__device__ float g_t[ROWS_TOTAL * R];   // 1 MB scratch (fully overwritten)

__device__ __forceinline__ u64 fma2(u64 a, u64 b, u64 c) {
    u64 d; asm("fma.rn.f32x2 %0,%1,%2,%3;" : "=l"(d) : "l"(a), "l"(b), "l"(c)); return d;
}
__device__ __forceinline__ u64 add2(u64 a, u64 b) {
    u64 d; asm("add.rn.f32x2 %0,%1,%2;" : "=l"(d) : "l"(a), "l"(b)); return d;
}
__device__ __forceinline__ u64 dup2(float s) {
    u64 d; asm("mov.b64 %0,{%1,%1};" : "=l"(d) : "f"(s)); return d;
}
__device__ __forceinline__ void unpack2(u64 v, float& lo, float& hi) {
    asm("mov.b64 {%0,%1},%2;" : "=f"(lo), "=f"(hi) : "l"(v));
}
__device__ __forceinline__ float hsum2(u64 v) {
    float lo, hi; unpack2(v, lo, hi); return lo + hi;
}

// ---------------- Stage 1: t = x @ A^T ----------------
// Block 256 thr / 8 warps, 64 rows per block, grid 256.
// Lane l owns rows (2l, 2l+1); acc[r] is f32x2 = (row-even, row-odd) sums.
// Warps split k: warp w owns k in [c*KC + w*16, +16) each chunk.
// x tile stored TRANSPOSED in smem (xsT[k][row]) with an XOR swizzle on the
// row index (s = seg<<3) so the transpose STS is bank-conflict-free while
// the LDG side stays fully coalesced. A chunk stored as duplicated f32x2
// table ad[k][r] so the inner loop's A reads are pure broadcasts.
__global__ void __launch_bounds__(256, 2)
lora_stage1(const float* __restrict__ x, const float* __restrict__ A)
{
    __shared__ __align__(16) unsigned char smem_raw[48 * 1024];
    float* xsT = (float*)smem_raw;                  // [KC][64]  32 KB
    u64*   ad  = (u64*)(smem_raw + KC * 64 * 4);    // [KC][16]  16 KB
    u64*   red = (u64*)smem_raw;                    // [8][32][17] reuse at end

    const int tid  = threadIdx.x;
    const int w    = tid >> 5;
    const int lane = tid & 31;
    const long rowBase = (long)blockIdx.x * 64;

    // x loader role: row = tid>>2 (0..63), seg = tid&3 (k window seg*32..+31)
    const int lrow = tid >> 2, seg = tid & 3;
    const int lrow_sw = lrow ^ (seg << 3);          // swizzled row for STS
    const float* xsrc = x + (rowBase + lrow) * D + seg * 32;

    // A loader role: r = tid&15, kg = tid>>4 (8 k each)
    const int ar = tid & 15, akg = tid >> 4;
    const float* asrc = A + (long)ar * D + akg * 8;

    u64 acc[16];
    #pragma unroll
    for (int r = 0; r < R; ++r) acc[r] = 0ULL;

    // prologue: prefetch chunk 0
    float4 xpf[8];
    float4 apf0, apf1;
    #pragma unroll
    for (int j = 0; j < 8; ++j) xpf[j] = *(const float4*)(xsrc + j * 4);
    apf0 = *(const float4*)(asrc);
    apf1 = *(const float4*)(asrc + 4);

    for (int c = 0; c < NCHUNK; ++c) {
        __syncthreads();   // previous chunk's smem fully consumed

        // ---- store prefetched x (transposed + swizzled) ----
        #pragma unroll
        for (int j = 0; j < 8; ++j) {
            const int k = seg * 32 + j * 4;
            xsT[(k + 0) * 64 + lrow_sw] = xpf[j].x;
            xsT[(k + 1) * 64 + lrow_sw] = xpf[j].y;
            xsT[(k + 2) * 64 + lrow_sw] = xpf[j].z;
            xsT[(k + 3) * 64 + lrow_sw] = xpf[j].w;
        }
        // ---- store prefetched A as duplicated f32x2 table ----
        {
            const int kb = akg * 8;
            ad[(kb + 0) * R + ar] = dup2(apf0.x);
            ad[(kb + 1) * R + ar] = dup2(apf0.y);
            ad[(kb + 2) * R + ar] = dup2(apf0.z);
            ad[(kb + 3) * R + ar] = dup2(apf0.w);
            ad[(kb + 4) * R + ar] = dup2(apf1.x);
            ad[(kb + 5) * R + ar] = dup2(apf1.y);
            ad[(kb + 6) * R + ar] = dup2(apf1.z);
            ad[(kb + 7) * R + ar] = dup2(apf1.w);
        }
        __syncthreads();

        // ---- prefetch next chunk (latency hidden by compute below) ----
        if (c + 1 < NCHUNK) {
            const float* xn = xsrc + (c + 1) * KC;
            #pragma unroll
            for (int j = 0; j < 8; ++j) xpf[j] = *(const float4*)(xn + j * 4);
            const float* an = asrc + (c + 1) * KC;
            apf0 = *(const float4*)(an);
            apf1 = *(const float4*)(an + 4);
        }

        // ---- compute: warp w handles k = w*16 .. w*16+15 of this chunk ----
        #pragma unroll
        for (int kk = 0; kk < 16; ++kk) {
            const int k = w * 16 + kk;
            const int rsw = (2 * lane) ^ (((k >> 5) & 3) << 3);
            const u64 xv = *(const u64*)(xsT + k * 64 + rsw);   // (x_row0, x_row1)
            const u64* adk = ad + k * R;
            #pragma unroll
            for (int rr = 0; rr < 8; ++rr) {
                // broadcast 16B: av for r=2rr, 2rr+1
                ulonglong2 av = *(const ulonglong2*)(adk + 2 * rr);
                acc[2 * rr]     = fma2(xv, av.x, acc[2 * rr]);
                acc[2 * rr + 1] = fma2(xv, av.y, acc[2 * rr + 1]);
            }
        }
    }

    // ---- cross-warp reduction (warps hold disjoint k partials) ----
    __syncthreads();   // done with xsT/ad, reuse as red[8][32][17]
    #pragma unroll
    for (int r = 0; r < R; ++r)
        red[(w * 32 + lane) * 17 + r] = acc[r];
    __syncthreads();

    // thread t: row-pair p = t>>3, r-pair r0 = (t&7)*2
    {
        const int p = tid >> 3;
        const int r0 = (tid & 7) * 2;
        u64 v0 = 0ULL, v1 = 0ULL;
        #pragma unroll
        for (int ww = 0; ww < 8; ++ww) {
            v0 = add2(v0, red[(ww * 32 + p) * 17 + r0]);
            v1 = add2(v1, red[(ww * 32 + p) * 17 + r0 + 1]);
        }
        float a0, a1, b0, b1;
        unpack2(v0, a0, a1);   // a0: row 2p, a1: row 2p+1 (for r0)
        unpack2(v1, b0, b1);
        *(float2*)(g_t + (rowBase + 2 * p) * R + r0)     = make_float2(a0, b0);
        *(float2*)(g_t + (rowBase + 2 * p + 1) * R + r0) = make_float2(a1, b1);
    }
}

// ---------------- Stage 2: out = t @ B^T ---------------- (unchanged, ~56us)
__global__ void __launch_bounds__(256, 2)
lora_stage2(const float* __restrict__ B, float* __restrict__ out)
{
    __shared__ float ts[128 * R];   // 8 KB

    const int tid = threadIdx.x;
    const long rowBase = (long)blockIdx.y * 128;
    const int ob = blockIdx.x * 1024 + tid * 4;

    *(float4*)(ts + tid * 8)     = *(const float4*)(g_t + rowBase * R + tid * 8);
    *(float4*)(ts + tid * 8 + 4) = *(const float4*)(g_t + rowBase * R + tid * 8 + 4);

    u64 bb[4][8];
    #pragma unroll
    for (int j = 0; j < 4; ++j) {
        const float* bp = B + (long)(ob + j) * R;
        ulonglong2 v0 = *(const ulonglong2*)(bp);
        ulonglong2 v1 = *(const ulonglong2*)(bp + 4);
        ulonglong2 v2 = *(const ulonglong2*)(bp + 8);
        ulonglong2 v3 = *(const ulonglong2*)(bp + 12);
        bb[j][0] = v0.x; bb[j][1] = v0.y;
        bb[j][2] = v1.x; bb[j][3] = v1.y;
        bb[j][4] = v2.x; bb[j][5] = v2.y;
        bb[j][6] = v3.x; bb[j][7] = v3.y;
    }
    __syncthreads();

    for (int row = 0; row < 128; ++row) {
        u64 tt[8];
        #pragma unroll
        for (int q = 0; q < 4; ++q) {
            ulonglong2 v = *(const ulonglong2*)(ts + row * R + q * 4);
            tt[2 * q]     = v.x;
            tt[2 * q + 1] = v.y;
        }
        float res[4];
        #pragma unroll
        for (int j = 0; j < 4; ++j) {
            u64 a = 0ULL;
            #pragma unroll
            for (int p = 0; p < 8; ++p)
                a = fma2(bb[j][p], tt[p], a);
            res[j] = hsum2(a);
        }
        *(float4*)(out + (rowBase + row) * (long)D + ob) =
            make_float4(res[0], res[1], res[2], res[3]);
    }
}

extern "C" void kernel_launch(void* const* d_in, const int* in_sizes, int n_in,
                              void* d_out, int out_size) {
    const float* x = (const float*)d_in[0];   // [16384, 4096]
    const float* A = (const float*)d_in[1];   // [16, 4096]
    const float* B = (const float*)d_in[2];   // [4096, 16]
    float* out = (float*)d_out;               // [16384, 4096]

    lora_stage1<<<ROWS_TOTAL / 64, 256>>>(x, A);
    dim3 g2(D / 1024, ROWS_TOTAL / 128);
    lora_stage2<<<g2, 256>>>(B, out);
}

// round 5
// speedup vs baseline: 1.6431x; 1.6431x over previous
#include <cuda_runtime.h>
#include <cstdint>

// LoRA linear via rank-16 factor:
//   t   = x @ A^T   : [16384,4096] @ [4096,16] -> [16384,16]   (stage 1)
//   out = t @ B^T   : [16384,16]   @ [16,4096] -> [16384,4096] (stage 2)

#define D 4096
#define R 16
#define ROWS_TOTAL 16384
#define KC 64
#define NCH (D / KC)    // 64 chunks
#define ADS 18          // ad row stride (u64) : 16B-aligned rows + bank spread

typedef unsigned long long u64;

__device__ float g_t[ROWS_TOTAL * R];   // 1 MB scratch (fully overwritten)

__device__ __forceinline__ u64 fma2(u64 a, u64 b, u64 c) {
    u64 d; asm("fma.rn.f32x2 %0,%1,%2,%3;" : "=l"(d) : "l"(a), "l"(b), "l"(c)); return d;
}
__device__ __forceinline__ u64 pack2(float lo, float hi) {
    u64 d; asm("mov.b64 %0,{%1,%2};" : "=l"(d) : "f"(lo), "f"(hi)); return d;
}
__device__ __forceinline__ float hsum2(u64 v) {
    float lo, hi; asm("mov.b64 {%0,%1},%2;" : "=f"(lo), "=f"(hi) : "l"(v)); return lo + hi;
}
__device__ __forceinline__ void cp16(uint32_t d, const void* s) {
    asm volatile("cp.async.cg.shared.global [%0],[%1],16;" :: "r"(d), "l"(s));
}
__device__ __forceinline__ void cpcommit() { asm volatile("cp.async.commit_group;"); }
__device__ __forceinline__ void cpwait1()  { asm volatile("cp.async.wait_group 1;"); }

// ---------------- Stage 1: t = x @ A^T ----------------
// Block 256 thr / 8 warps, 64 rows, grid 256. Lane owns rows (2l, 2l+1).
// Warps split k 8-way (8 k = 4 k-pairs per warp per chunk).
// f32x2 packing over (k-even, k-odd): x pairs come free from LDS.128;
// A pre-packed in ad[kpair][r]; all A reads are warp-broadcast (1 phase).
// x staged row-major (stride 64) with 16B XOR swizzle; cp.async double buffer.
__global__ void __launch_bounds__(256, 2)
lora_stage1(const float* __restrict__ x, const float* __restrict__ A)
{
    __shared__ __align__(16) unsigned char sm[37 * 1024];
    float* xs  = (float*)sm;                 // [2][64][64]  32 KB
    u64*   ad  = (u64*)(sm + 32768);         // [32][ADS]    4.6 KB
    float* redf = (float*)sm;                // [8][64*17]   34.8 KB overlay

    const int tid  = threadIdx.x;
    const int w    = tid >> 5;
    const int lane = tid & 31;
    const long rowBase = (long)blockIdx.x * 64;

    // x cp.async loader role: row = tid>>2, 16-float segment = tid&3
    const int trow = tid >> 2, tseg = tid & 3;
    const int tswz = ((trow >> 1) & 7) << 2;
    const float* xsrc = x + (rowBase + trow) * D;
    const uint32_t xs_sh = (uint32_t)__cvta_generic_to_shared(sm);

    // A loader role: lane = kpair (coalesced float2 LDG), warp picks r-pair
    const int akp = tid & 31;
    const int ar  = (tid >> 5) * 2;
    const float* asrc0 = A + (long)ar * D + 2 * akp;
    const float* asrc1 = asrc0 + D;

    // compute-role constants
    const int r0   = 2 * lane;               // even row
    const int csw  = (lane & 7) << 2;
    const int col0 = (w * 8) ^ csw;          // k-group 0 (k = w*8 .. +3)
    const int col1 = (w * 8 + 4) ^ csw;      // k-group 1

    u64 acc0[16], acc1[16];
    #pragma unroll
    for (int r = 0; r < 16; ++r) { acc0[r] = 0ULL; acc1[r] = 0ULL; }

    // ---- prologue: chunk 0 x in flight, A(0) in regs ----
    #pragma unroll
    for (int j = 0; j < 4; ++j) {
        const int k = tseg * 16 + j * 4;
        cp16(xs_sh + (uint32_t)(trow * 64 + (k ^ tswz)) * 4u, xsrc + k);
    }
    cpcommit();
    float2 a0 = *(const float2*)asrc0;
    float2 a1 = *(const float2*)asrc1;

    for (int c = 0; c < NCH; ++c) {
        const int b = c & 1;
        __syncthreads();   // barrier A: compute(c-1) done -> other buf + ad free

        if (c + 1 < NCH) {
            #pragma unroll
            for (int j = 0; j < 4; ++j) {
                const int k = tseg * 16 + j * 4;
                cp16(xs_sh + (uint32_t)((b ^ 1) * 4096 + trow * 64 + (k ^ tswz)) * 4u,
                     xsrc + (c + 1) * KC + k);
            }
        }
        cpcommit();   // always commit (maybe empty) so wait1 == "chunk c landed"

        // store A(c) pairs; prefetch A(c+1)
        ad[akp * ADS + ar]     = pack2(a0.x, a0.y);
        ad[akp * ADS + ar + 1] = pack2(a1.x, a1.y);
        if (c + 1 < NCH) {
            a0 = *(const float2*)(asrc0 + (c + 1) * KC);
            a1 = *(const float2*)(asrc1 + (c + 1) * KC);
        }

        cpwait1();
        __syncthreads();   // barrier B: buf b + ad(c) visible

        // ---- compute chunk c ----
        const float* xb = xs + b * 4096;
        ulonglong2 xa = *(const ulonglong2*)(xb + r0 * 64 + col0);
        ulonglong2 xc = *(const ulonglong2*)(xb + r0 * 64 + col1);
        ulonglong2 ya = *(const ulonglong2*)(xb + (r0 + 1) * 64 + col0);
        ulonglong2 yc = *(const ulonglong2*)(xb + (r0 + 1) * 64 + col1);
        u64 xk[4] = { xa.x, xa.y, xc.x, xc.y };   // k-pairs kp = w*4 + 0..3
        u64 yk[4] = { ya.x, ya.y, yc.x, yc.y };

        #pragma unroll
        for (int kp2 = 0; kp2 < 4; ++kp2) {
            const u64* adk = ad + (w * 4 + kp2) * ADS;
            const u64 xv = xk[kp2], yv = yk[kp2];
            #pragma unroll
            for (int rr = 0; rr < 8; ++rr) {
                ulonglong2 av = *(const ulonglong2*)(adk + 2 * rr);  // broadcast
                acc0[2 * rr]     = fma2(xv, av.x, acc0[2 * rr]);
                acc0[2 * rr + 1] = fma2(xv, av.y, acc0[2 * rr + 1]);
                acc1[2 * rr]     = fma2(yv, av.x, acc1[2 * rr]);
                acc1[2 * rr + 1] = fma2(yv, av.y, acc1[2 * rr + 1]);
            }
        }
    }

    // ---- cross-warp reduction (warps hold disjoint k partials) ----
    __syncthreads();   // done with xs/ad -> overlay redf
    #pragma unroll
    for (int r = 0; r < 16; ++r) {
        redf[w * 1088 + (r0)     * 17 + r] = hsum2(acc0[r]);
        redf[w * 1088 + (r0 + 1) * 17 + r] = hsum2(acc1[r]);
    }
    __syncthreads();

    #pragma unroll
    for (int i = 0; i < 4; ++i) {
        const int e = tid + 256 * i;          // 0..1023
        const int row = e >> 4, r = e & 15;
        float s = 0.f;
        #pragma unroll
        for (int ww = 0; ww < 8; ++ww)
            s += redf[ww * 1088 + row * 17 + r];
        g_t[(rowBase + row) * R + r] = s;
    }
}

// ---------------- Stage 2: out = t @ B^T ---------------- (known-good, ~55us)
__global__ void __launch_bounds__(256, 2)
lora_stage2(const float* __restrict__ B, float* __restrict__ out)
{
    __shared__ float ts[128 * R];   // 8 KB

    const int tid = threadIdx.x;
    const long rowBase = (long)blockIdx.y * 128;
    const int ob = blockIdx.x * 1024 + tid * 4;

    *(float4*)(ts + tid * 8)     = *(const float4*)(g_t + rowBase * R + tid * 8);
    *(float4*)(ts + tid * 8 + 4) = *(const float4*)(g_t + rowBase * R + tid * 8 + 4);

    u64 bb[4][8];
    #pragma unroll
    for (int j = 0; j < 4; ++j) {
        const float* bp = B + (long)(ob + j) * R;
        ulonglong2 v0 = *(const ulonglong2*)(bp);
        ulonglong2 v1 = *(const ulonglong2*)(bp + 4);
        ulonglong2 v2 = *(const ulonglong2*)(bp + 8);
        ulonglong2 v3 = *(const ulonglong2*)(bp + 12);
        bb[j][0] = v0.x; bb[j][1] = v0.y;
        bb[j][2] = v1.x; bb[j][3] = v1.y;
        bb[j][4] = v2.x; bb[j][5] = v2.y;
        bb[j][6] = v3.x; bb[j][7] = v3.y;
    }
    __syncthreads();

    for (int row = 0; row < 128; ++row) {
        u64 tt[8];
        #pragma unroll
        for (int q = 0; q < 4; ++q) {
            ulonglong2 v = *(const ulonglong2*)(ts + row * R + q * 4);
            tt[2 * q]     = v.x;
            tt[2 * q + 1] = v.y;
        }
        float res[4];
        #pragma unroll
        for (int j = 0; j < 4; ++j) {
            u64 a = 0ULL;
            #pragma unroll
            for (int p = 0; p < 8; ++p)
                a = fma2(bb[j][p], tt[p], a);
            res[j] = hsum2(a);
        }
        *(float4*)(out + (rowBase + row) * (long)D + ob) =
            make_float4(res[0], res[1], res[2], res[3]);
    }
}

extern "C" void kernel_launch(void* const* d_in, const int* in_sizes, int n_in,
                              void* d_out, int out_size) {
    const float* x = (const float*)d_in[0];   // [16384, 4096]
    const float* A = (const float*)d_in[1];   // [16, 4096]
    const float* B = (const float*)d_in[2];   // [4096, 16]
    float* out = (float*)d_out;               // [16384, 4096]

    lora_stage1<<<ROWS_TOTAL / 64, 256>>>(x, A);
    dim3 g2(D / 1024, ROWS_TOTAL / 128);
    lora_stage2<<<g2, 256>>>(B, out);
}

// round 6
// speedup vs baseline: 1.7148x; 1.0436x over previous
#include <cuda_runtime.h>
#include <cstdint>

// LoRA linear via rank-16 factor:
//   t   = x @ A^T   : [16384,4096] @ [4096,16] -> [16384,16]   (stage 1)
//   out = t @ B^T   : [16384,16]   @ [16,4096] -> [16384,4096] (stage 2)

#define D 4096
#define R 16
#define ROWS_TOTAL 16384
#define KC 32
#define NCH (D / KC)        // 128 chunks
#define ADS 18              // ad row stride in u64 (16B-aligned rows, bank spread)
#define AD_STAGE (16 * ADS) // 288 u64 per stage

typedef unsigned long long u64;

__device__ float g_t[ROWS_TOTAL * R];   // 1 MB scratch (fully overwritten)

__device__ __forceinline__ u64 fma2(u64 a, u64 b, u64 c) {
    u64 d; asm("fma.rn.f32x2 %0,%1,%2,%3;" : "=l"(d) : "l"(a), "l"(b), "l"(c)); return d;
}
__device__ __forceinline__ u64 pack2(float lo, float hi) {
    u64 d; asm("mov.b64 %0,{%1,%2};" : "=l"(d) : "f"(lo), "f"(hi)); return d;
}
__device__ __forceinline__ float hsum2(u64 v) {
    float lo, hi; asm("mov.b64 {%0,%1},%2;" : "=f"(lo), "=f"(hi) : "l"(v)); return lo + hi;
}
__device__ __forceinline__ void cp16(uint32_t d, const void* s) {
    asm volatile("cp.async.cg.shared.global [%0],[%1],16;" :: "r"(d), "l"(s));
}
__device__ __forceinline__ void cpcommit() { asm volatile("cp.async.commit_group;"); }
__device__ __forceinline__ void cpwait2()  { asm volatile("cp.async.wait_group 2;"); }

// ---------------- Stage 1: t = x @ A^T ----------------
// Block 256 thr / 8 warps, 64 rows, grid 256. Lane owns rows (2l, 2l+1);
// f32x2 packed over (k-even,k-odd); warp w owns k = w*4..w*4+3 per chunk.
// 4-stage cp.async ring, ONE __syncthreads per chunk, wait_group 2 keeps
// 3 chunks (24 KB) in flight per block. A staged 2 chunks ahead via regs;
// ad[kp][r] f32x2 table -> all A reads are warp-broadcast LDS.128.
__global__ void __launch_bounds__(256, 2)
lora_stage1(const float* __restrict__ x, const float* __restrict__ A)
{
    __shared__ __align__(16) unsigned char sm[42 * 1024];
    float* xs = (float*)sm;                  // [4][64][32]  32 KB
    u64*   ad = (u64*)(sm + 32768);          // [4][16][ADS] 9.2 KB
    float* redf = (float*)sm;                // [8][64*17]   34.8 KB overlay

    const int tid  = threadIdx.x;
    const int w    = tid >> 5;
    const int lane = tid & 31;
    const long rowBase = (long)blockIdx.x * 64;

    // x cp.async loader role: row = tid>>2, seg = tid&3 (8 floats each)
    const int trow = tid >> 2, tseg = tid & 3;
    const int tsw  = (trow >> 1) & 7;
    const int tph0 = (2 * tseg)     ^ tsw;   // physical 16B slot 0
    const int tph1 = (2 * tseg + 1) ^ tsw;   // physical 16B slot 1
    const float* xsrc = x + (rowBase + trow) * D;
    const uint32_t xs_sh = (uint32_t)__cvta_generic_to_shared(sm);

    // A loader role: r = tid>>4, kp = tid&15 (coalesced float2 per row)
    const int ar = tid >> 4, akp = tid & 15;
    const float* asrc = A + (long)ar * D + 2 * akp;

    // compute-role constants
    const int r0  = 2 * lane;                        // even row
    const int pcs = (w ^ (lane & 7)) * 4;            // phys col offset (floats)

    u64 acc0[16], acc1[16];
    #pragma unroll
    for (int r = 0; r < 16; ++r) { acc0[r] = 0ULL; acc1[r] = 0ULL; }

    // ---- prologue: x chunks 0..2 in flight, A(0..1) in smem, A(2) in regs ----
    #pragma unroll
    for (int cc = 0; cc < 3; ++cc) {
        const float* xp = xsrc + cc * KC + tseg * 8;
        cp16(xs_sh + (uint32_t)(cc * 2048 + trow * 32 + tph0 * 4) * 4u, xp);
        cp16(xs_sh + (uint32_t)(cc * 2048 + trow * 32 + tph1 * 4) * 4u, xp + 4);
        cpcommit();
    }
    {
        float2 t0 = *(const float2*)(asrc);
        float2 t1 = *(const float2*)(asrc + KC);
        ad[0 * AD_STAGE + akp * ADS + ar] = pack2(t0.x, t0.y);
        ad[1 * AD_STAGE + akp * ADS + ar] = pack2(t1.x, t1.y);
    }
    float2 apf = *(const float2*)(asrc + 2 * KC);

    #pragma unroll 4
    for (int c = 0; c < NCH; ++c) {
        const int s = c & 3;
        cpwait2();           // chunk c's group landed (this thread)
        __syncthreads();     // all threads' data visible + compute(c-1) done

        // fill slot (c+3)&3 (held x(c-1), now free)
        if (c + 3 < NCH) {
            const float* xp = xsrc + (c + 3) * KC + tseg * 8;
            const uint32_t base = (uint32_t)(((c + 3) & 3) * 2048 + trow * 32);
            cp16(xs_sh + (base + tph0 * 4) * 4u, xp);
            cp16(xs_sh + (base + tph1 * 4) * 4u, xp + 4);
        }
        cpcommit();          // always commit so group count tracks chunks

        // stage A(c+2) into its slot; prefetch A(c+3) into regs
        if (c + 2 < NCH)
            ad[((c + 2) & 3) * AD_STAGE + akp * ADS + ar] = pack2(apf.x, apf.y);
        if (c + 3 < NCH)
            apf = *(const float2*)(asrc + (c + 3) * KC);

        // ---- compute chunk c: k = w*4 .. w*4+3 (k-pairs w*2, w*2+1) ----
        const float* xb = xs + s * 2048;
        ulonglong2 xa = *(const ulonglong2*)(xb + r0 * 32 + pcs);        // row even
        ulonglong2 ya = *(const ulonglong2*)(xb + (r0 + 1) * 32 + pcs);  // row odd
        #pragma unroll
        for (int kp2 = 0; kp2 < 2; ++kp2) {
            const u64 xv = kp2 ? xa.y : xa.x;
            const u64 yv = kp2 ? ya.y : ya.x;
            const u64* adk = ad + s * AD_STAGE + (w * 2 + kp2) * ADS;
            #pragma unroll
            for (int rr = 0; rr < 8; ++rr) {
                ulonglong2 av = *(const ulonglong2*)(adk + 2 * rr);  // broadcast
                acc0[2 * rr]     = fma2(xv, av.x, acc0[2 * rr]);
                acc0[2 * rr + 1] = fma2(xv, av.y, acc0[2 * rr + 1]);
                acc1[2 * rr]     = fma2(yv, av.x, acc1[2 * rr]);
                acc1[2 * rr + 1] = fma2(yv, av.y, acc1[2 * rr + 1]);
            }
        }
    }

    // ---- cross-warp reduction (warps hold disjoint k partials) ----
    __syncthreads();   // done with xs/ad -> overlay redf
    #pragma unroll
    for (int r = 0; r < 16; ++r) {
        redf[w * 1088 + (r0)     * 17 + r] = hsum2(acc0[r]);
        redf[w * 1088 + (r0 + 1) * 17 + r] = hsum2(acc1[r]);
    }
    __syncthreads();

    #pragma unroll
    for (int i = 0; i < 4; ++i) {
        const int e = tid + 256 * i;          // 0..1023
        const int row = e >> 4, r = e & 15;
        float s = 0.f;
        #pragma unroll
        for (int ww = 0; ww < 8; ++ww)
            s += redf[ww * 1088 + row * 17 + r];
        g_t[(rowBase + row) * R + r] = s;
    }
}

// ---------------- Stage 2: out = t @ B^T ---------------- (known-good, ~55us)
__global__ void __launch_bounds__(256, 2)
lora_stage2(const float* __restrict__ B, float* __restrict__ out)
{
    __shared__ float ts[128 * R];   // 8 KB

    const int tid = threadIdx.x;
    const long rowBase = (long)blockIdx.y * 128;
    const int ob = blockIdx.x * 1024 + tid * 4;

    *(float4*)(ts + tid * 8)     = *(const float4*)(g_t + rowBase * R + tid * 8);
    *(float4*)(ts + tid * 8 + 4) = *(const float4*)(g_t + rowBase * R + tid * 8 + 4);

    u64 bb[4][8];
    #pragma unroll
    for (int j = 0; j < 4; ++j) {
        const float* bp = B + (long)(ob + j) * R;
        ulonglong2 v0 = *(const ulonglong2*)(bp);
        ulonglong2 v1 = *(const ulonglong2*)(bp + 4);
        ulonglong2 v2 = *(const ulonglong2*)(bp + 8);
        ulonglong2 v3 = *(const ulonglong2*)(bp + 12);
        bb[j][0] = v0.x; bb[j][1] = v0.y;
        bb[j][2] = v1.x; bb[j][3] = v1.y;
        bb[j][4] = v2.x; bb[j][5] = v2.y;
        bb[j][6] = v3.x; bb[j][7] = v3.y;
    }
    __syncthreads();

    for (int row = 0; row < 128; ++row) {
        u64 tt[8];
        #pragma unroll
        for (int q = 0; q < 4; ++q) {
            ulonglong2 v = *(const ulonglong2*)(ts + row * R + q * 4);
            tt[2 * q]     = v.x;
            tt[2 * q + 1] = v.y;
        }
        float res[4];
        #pragma unroll
        for (int j = 0; j < 4; ++j) {
            u64 a = 0ULL;
            #pragma unroll
            for (int p = 0; p < 8; ++p)
                a = fma2(bb[j][p], tt[p], a);
            res[j] = hsum2(a);
        }
        *(float4*)(out + (rowBase + row) * (long)D + ob) =
            make_float4(res[0], res[1], res[2], res[3]);
    }
}

extern "C" void kernel_launch(void* const* d_in, const int* in_sizes, int n_in,
                              void* d_out, int out_size) {
    const float* x = (const float*)d_in[0];   // [16384, 4096]
    const float* A = (const float*)d_in[1];   // [16, 4096]
    const float* B = (const float*)d_in[2];   // [4096, 16]
    float* out = (float*)d_out;               // [16384, 4096]

    lora_stage1<<<ROWS_TOTAL / 64, 256>>>(x, A);
    dim3 g2(D / 1024, ROWS_TOTAL / 128);
    lora_stage2<<<g2, 256>>>(B, out);
}